// round 1
// baseline (speedup 1.0000x reference)
#include <cuda_runtime.h>
#include <cuda_bf16.h>
#include <math.h>

// ---------------------------------------------------------------------------
// PhysicsAwareMSELoss
//   inputs (metadata order):
//     0: pred             float32 [B,S,1]
//     1: target           float32 [B,S,1]
//     2: material_ids     int32   [B]
//     3: strain_seq_raw   float32 [B,S]
//     4: E_GPa            float32 [B]
//     5: temperature_raw  float32 [B]
//     6: strain_rate_raw  float32 [B]
//     7: material_weights float32 [NUM_MAT]
//   output: scalar float32 loss
// ---------------------------------------------------------------------------

#define MAXB 256
#define ALPHA 0.7f
#define BETA  0.3f

// scratch (device globals; no allocations allowed)
__device__ float g_mse [MAXB];   // sum (pred-target)^2 over S
__device__ float g_cnt [MAXB];   // # of strain < 0.02
__device__ float g_Sx  [MAXB];   // sum strain * m
__device__ float g_Sy  [MAXB];   // sum stress * m
__device__ float g_Sxy [MAXB];   // sum strain*stress * m
__device__ float g_Sxx [MAXB];   // sum strain^2 * m
__device__ float g_mono[MAXB];   // sum relu(s[t]-s[t+1])
__device__ float g_pairD[MAXB * MAXB];

// --------------------------------------------------------------------------
// Kernel A: per-sample reductions. One block per sample b.
// --------------------------------------------------------------------------
__global__ void stats_kernel(const float* __restrict__ pred,
                             const float* __restrict__ target,
                             const float* __restrict__ strain,
                             int S)
{
    const int b = blockIdx.x;
    const float* p = pred   + (size_t)b * S;
    const float* t = target + (size_t)b * S;
    const float* e = strain + (size_t)b * S;

    float d2 = 0.f, cnt = 0.f, sx = 0.f, sy = 0.f, sxy = 0.f, sxx = 0.f, mono = 0.f;

    for (int i = threadIdx.x; i < S; i += blockDim.x) {
        float pv = p[i];
        float tv = t[i];
        float ev = e[i];
        float d  = pv - tv;
        d2 += d * d;
        if (ev < 0.02f) {
            cnt += 1.f;
            sx  += ev;
            sy  += pv;
            sxy += ev * pv;
            sxx += ev * ev;
        }
        if (i < S - 1) {
            float df = pv - p[i + 1];
            mono += (df > 0.f) ? df : 0.f;
        }
    }

    // block tree-reduce (deterministic)
    __shared__ float sh[7][256];
    sh[0][threadIdx.x] = d2;
    sh[1][threadIdx.x] = cnt;
    sh[2][threadIdx.x] = sx;
    sh[3][threadIdx.x] = sy;
    sh[4][threadIdx.x] = sxy;
    sh[5][threadIdx.x] = sxx;
    sh[6][threadIdx.x] = mono;
    __syncthreads();
    for (int s = blockDim.x >> 1; s > 0; s >>= 1) {
        if (threadIdx.x < s) {
            #pragma unroll
            for (int k = 0; k < 7; k++)
                sh[k][threadIdx.x] += sh[k][threadIdx.x + s];
        }
        __syncthreads();
    }
    if (threadIdx.x == 0) {
        g_mse [b] = sh[0][0];
        g_cnt [b] = sh[1][0];
        g_Sx  [b] = sh[2][0];
        g_Sy  [b] = sh[3][0];
        g_Sxy [b] = sh[4][0];
        g_Sxx [b] = sh[5][0];
        g_mono[b] = sh[6][0];
    }
}

// --------------------------------------------------------------------------
// Kernel B: pairwise D (sparse). One warp per (i,j) pair.
// D[i,j] is only computed where tmask(i,j) or smask(j,i) holds.
// --------------------------------------------------------------------------
__device__ __forceinline__ void pair_masks(int mi, int mj,
                                           float sri, float srj,
                                           float ti, float tj,
                                           bool& tmask_ij, bool& smask_ij)
{
    bool same   = (mi == mj);
    float hi    = fmaxf(sri, srj);
    float lo    = fminf(sri, srj);
    float ratio = hi / (lo + 1e-8f);
    float tdiff = ti - tj;
    tmask_ij = same && (ratio <= 1.2f) && (fabsf(tdiff) >= 10.f) && (tdiff > 0.f);
    smask_ij = same && (fabsf(tdiff) <= 10.f) && (ratio >= 1.2f) && (sri > srj);
}

__global__ void pair_kernel(const float* __restrict__ stress,
                            const int*   __restrict__ mat,
                            const float* __restrict__ temp,
                            const float* __restrict__ sr,
                            int B, int S)
{
    int warp = (blockIdx.x * blockDim.x + threadIdx.x) >> 5;
    int lane = threadIdx.x & 31;
    if (warp >= B * B) return;
    int i = warp / B;
    int j = warp - i * B;

    // need D[i,j] iff tmask(i,j) or smask(j,i)
    bool t_ij, s_ij_dummy, t_ji_dummy, s_ji;
    pair_masks(mat[i], mat[j], sr[i], sr[j], temp[i], temp[j], t_ij, s_ij_dummy);
    pair_masks(mat[j], mat[i], sr[j], sr[i], temp[j], temp[i], t_ji_dummy, s_ji);
    bool need = t_ij || s_ji;

    if (!need) {
        if (lane == 0) g_pairD[i * B + j] = 0.f;
        return;
    }

    const float* si = stress + (size_t)i * S;
    const float* sj = stress + (size_t)j * S;
    float acc = 0.f;
    for (int t = lane; t < S; t += 32) {
        float d = si[t] - sj[t];
        acc += fmaxf(d, 0.f);
    }
    #pragma unroll
    for (int off = 16; off > 0; off >>= 1)
        acc += __shfl_xor_sync(0xFFFFFFFFu, acc, off);
    if (lane == 0) g_pairD[i * B + j] = acc / (float)S;
}

// --------------------------------------------------------------------------
// Kernel C: final combine (one block).
// --------------------------------------------------------------------------
__global__ void final_kernel(const int*   __restrict__ mat,
                             const float* __restrict__ w,
                             const float* __restrict__ E,
                             const float* __restrict__ temp,
                             const float* __restrict__ sr,
                             float* __restrict__ out,
                             int B, int S)
{
    float mse_p = 0.f, el_sum = 0.f, el_cnt = 0.f, mono_p = 0.f;

    for (int b = threadIdx.x; b < B; b += blockDim.x) {
        mse_p  += (g_mse[b] / (float)S) * w[mat[b]];
        mono_p += g_mono[b];
        float cnt = g_cnt[b];
        if (cnt >= 2.f) {
            float safe  = fmaxf(cnt, 1.f);
            float eps_m = g_Sx[b] / safe;
            float sig_m = g_Sy[b] / safe;
            // cov = sum m*(x-eps_m)*(y-sig_m); var = sum m*(x-eps_m)^2
            float cov = g_Sxy[b] - sig_m * g_Sx[b] - eps_m * g_Sy[b] + cnt * eps_m * sig_m;
            float var = g_Sxx[b] - 2.f * eps_m * g_Sx[b] + cnt * eps_m * eps_m;
            float et  = E[b] * 1000.f;
            float err = fabsf(cov / (var + 1e-8f) - et) / (et + 1e-8f);
            el_sum += err;
            el_cnt += 1.f;
        }
    }

    float tsum = 0.f, tcnt = 0.f, ssum = 0.f, scnt = 0.f;
    for (int idx = threadIdx.x; idx < B * B; idx += blockDim.x) {
        int i = idx / B;
        int j = idx - i * B;
        bool t_ij, s_ij;
        pair_masks(mat[i], mat[j], sr[i], sr[j], temp[i], temp[j], t_ij, s_ij);
        if (t_ij) { tsum += g_pairD[i * B + j]; tcnt += 1.f; }
        if (s_ij) { ssum += g_pairD[j * B + i]; scnt += 1.f; }
    }

    __shared__ float sh[8][256];
    sh[0][threadIdx.x] = mse_p;
    sh[1][threadIdx.x] = el_sum;
    sh[2][threadIdx.x] = el_cnt;
    sh[3][threadIdx.x] = mono_p;
    sh[4][threadIdx.x] = tsum;
    sh[5][threadIdx.x] = tcnt;
    sh[6][threadIdx.x] = ssum;
    sh[7][threadIdx.x] = scnt;
    __syncthreads();
    for (int s = blockDim.x >> 1; s > 0; s >>= 1) {
        if (threadIdx.x < s) {
            #pragma unroll
            for (int k = 0; k < 8; k++)
                sh[k][threadIdx.x] += sh[k][threadIdx.x + s];
        }
        __syncthreads();
    }

    if (threadIdx.x == 0) {
        float mse_loss  = sh[0][0] / (float)B;
        float elastic   = (sh[2][0] > 0.f) ? sh[1][0] / fmaxf(sh[2][0], 1.f) : 0.f;
        float mono      = sh[3][0] / (float)(B * (S - 1));
        float temp_loss = (sh[5][0] > 0.f) ? sh[4][0] / fmaxf(sh[5][0], 1.f) : 0.f;
        float sr_loss   = (sh[7][0] > 0.f) ? sh[6][0] / fmaxf(sh[7][0], 1.f) : 0.f;
        float physics   = elastic + mono + temp_loss + sr_loss;
        out[0] = ALPHA * mse_loss + BETA * physics;
    }
}

// --------------------------------------------------------------------------
extern "C" void kernel_launch(void* const* d_in, const int* in_sizes, int n_in,
                              void* d_out, int out_size)
{
    const float* pred   = (const float*)d_in[0];
    const float* target = (const float*)d_in[1];
    const int*   matid  = (const int*)  d_in[2];
    const float* strain = (const float*)d_in[3];
    const float* E_GPa  = (const float*)d_in[4];
    const float* temp   = (const float*)d_in[5];
    const float* sr     = (const float*)d_in[6];
    const float* mw     = (const float*)d_in[7];
    float* out = (float*)d_out;

    const int B = in_sizes[2];          // material_ids count
    const int S = in_sizes[0] / B;      // pred = B*S

    stats_kernel<<<B, 256>>>(pred, target, strain, S);

    int warps  = B * B;
    int blocks = (warps * 32 + 255) / 256;
    pair_kernel<<<blocks, 256>>>(pred, matid, temp, sr, B, S);

    final_kernel<<<1, 256>>>(matid, mw, E_GPa, temp, sr, out, B, S);
}

// round 2
// speedup vs baseline: 1.1504x; 1.1504x over previous
#include <cuda_runtime.h>
#include <cuda_bf16.h>
#include <math.h>

// ---------------------------------------------------------------------------
// PhysicsAwareMSELoss — single fused kernel.
//   inputs (metadata order):
//     0: pred             float32 [B,S,1]
//     1: target           float32 [B,S,1]
//     2: material_ids     int32   [B]
//     3: strain_seq_raw   float32 [B,S]
//     4: E_GPa            float32 [B]
//     5: temperature_raw  float32 [B]
//     6: strain_rate_raw  float32 [B]
//     7: material_weights float32 [NUM_MAT]
//   output: scalar float32 loss
//
// Layout: grid = statsBlocks + pairBlocks.
//   stats blocks: per (sample, chunk) partial reductions, float4 loads.
//   pair blocks : 1 warp per (i,j) pair; scalar-mask screen, compute only
//                 the ~dozens of pairs the masks actually consume.
//   epilogue    : threadfence + atomic ticket; last block does the final
//                 combine and writes out[0], then resets the ticket.
// ---------------------------------------------------------------------------

#define MAXB   256
#define MAXCH  16
#define ALPHA  0.7f
#define BETA   0.3f

// scratch (device globals; allocations are forbidden)
__device__ float g_part[7][MAXB * MAXCH];   // 0:mse 1:cnt 2:Sx 3:Sy 4:Sxy 5:Sxx 6:mono
__device__ float g_pairD[MAXB * MAXB];      // only mask-needed entries written
__device__ unsigned int g_ticket;           // zero-init; reset by last block

__device__ __forceinline__ float reluf(float x) { return fmaxf(x, 0.f); }

__device__ __forceinline__ void pair_masks(int mi, int mj,
                                           float sri, float srj,
                                           float ti, float tj,
                                           bool& tmask_ij, bool& smask_ij)
{
    bool same   = (mi == mj);
    float hi    = fmaxf(sri, srj);
    float lo    = fminf(sri, srj);
    float ratio = hi / (lo + 1e-8f);
    float tdiff = ti - tj;
    tmask_ij = same && (ratio <= 1.2f) && (fabsf(tdiff) >= 10.f) && (tdiff > 0.f);
    smask_ij = same && (fabsf(tdiff) <= 10.f) && (ratio >= 1.2f) && (sri > srj);
}

__global__ void __launch_bounds__(256)
fused_kernel(const float* __restrict__ pred,
             const float* __restrict__ target,
             const int*   __restrict__ mat,
             const float* __restrict__ strain,
             const float* __restrict__ E,
             const float* __restrict__ temp,
             const float* __restrict__ sr,
             const float* __restrict__ w,
             float* __restrict__ out,
             int B, int S, int nChunk, int statsBlocks, int pairBlocks)
{
    const int tid  = threadIdx.x;
    const int lane = tid & 31;
    const int wid  = tid >> 5;

    __shared__ float sh[8][256];
    __shared__ bool  sh_last;

    // =================== role 1: per-sample stats (chunked) ===================
    if (blockIdx.x < statsBlocks) {
        const int b = blockIdx.x / nChunk;
        const int c = blockIdx.x % nChunk;
        const float* p = pred   + (size_t)b * S;
        const float* t = target + (size_t)b * S;
        const float* e = strain + (size_t)b * S;

        float d2 = 0.f, cnt = 0.f, sx = 0.f, sy = 0.f, sxy = 0.f, sxx = 0.f, mono = 0.f;

        const int e0 = c * 1024 + tid * 4;   // chunk = 256 threads * 4 elems
        if (e0 + 3 < S) {
            float4 pv = *reinterpret_cast<const float4*>(p + e0);
            float4 tv = *reinterpret_cast<const float4*>(t + e0);
            float4 ev = *reinterpret_cast<const float4*>(e + e0);

            float dx = pv.x - tv.x, dy = pv.y - tv.y, dz = pv.z - tv.z, dw = pv.w - tv.w;
            d2 = dx*dx + dy*dy + dz*dz + dw*dw;

            if (ev.x < 0.02f) { cnt += 1.f; sx += ev.x; sy += pv.x; sxy += ev.x*pv.x; sxx += ev.x*ev.x; }
            if (ev.y < 0.02f) { cnt += 1.f; sx += ev.y; sy += pv.y; sxy += ev.y*pv.y; sxx += ev.y*ev.y; }
            if (ev.z < 0.02f) { cnt += 1.f; sx += ev.z; sy += pv.z; sxy += ev.z*pv.z; sxx += ev.z*ev.z; }
            if (ev.w < 0.02f) { cnt += 1.f; sx += ev.w; sy += pv.w; sxy += ev.w*pv.w; sxx += ev.w*ev.w; }

            mono = reluf(pv.x - pv.y) + reluf(pv.y - pv.z) + reluf(pv.z - pv.w);
            // cross-element boundary: next = element e0+4
            float nxt = __shfl_down_sync(0xFFFFFFFFu, pv.x, 1);
            if (lane == 31) nxt = (e0 + 4 < S) ? p[e0 + 4] : pv.w;  // pv.w => relu 0
            if (e0 + 4 <= S - 1 || (e0 + 4 == S)) { /* keep semantics below */ }
            if (e0 + 4 < S || (lane != 31)) {
                // lanes 0..30 always have valid next (element within chunk);
                // lane 31 only adds if e0+4 < S (handled by nxt=pv.w otherwise)
            }
            mono += reluf(pv.w - nxt);
        } else if (e0 < S) {
            // scalar tail (unused for S=2048, kept for generality)
            for (int i = e0; i < S && i < e0 + 4; i++) {
                float pv = p[i], tv = t[i], ev = e[i];
                float d = pv - tv; d2 += d * d;
                if (ev < 0.02f) { cnt += 1.f; sx += ev; sy += pv; sxy += ev*pv; sxx += ev*ev; }
                if (i < S - 1) mono += reluf(pv - p[i + 1]);
            }
        }

        sh[0][tid]=d2; sh[1][tid]=cnt; sh[2][tid]=sx; sh[3][tid]=sy;
        sh[4][tid]=sxy; sh[5][tid]=sxx; sh[6][tid]=mono;
        __syncthreads();
        for (int s = 128; s > 0; s >>= 1) {
            if (tid < s) {
                #pragma unroll
                for (int k = 0; k < 7; k++) sh[k][tid] += sh[k][tid + s];
            }
            __syncthreads();
        }
        if (tid == 0) {
            const int slot = b * nChunk + c;
            #pragma unroll
            for (int k = 0; k < 7; k++) g_part[k][slot] = sh[k][0];
        }
    }
    // =================== role 2: sparse pairwise D ===================
    else {
        const int pairBase = (blockIdx.x - statsBlocks) * 8;   // 8 warps/block
        const int pairIdx  = pairBase + wid;
        if (pairIdx < B * B) {
            const int i = pairIdx / B;
            const int j = pairIdx - i * B;
            // need D[i,j] iff tmask(i,j) or smask(j,i)
            int   mi = __ldg(mat + i),  mj = __ldg(mat + j);
            float sri = __ldg(sr + i),  srj = __ldg(sr + j);
            float ti  = __ldg(temp + i), tj = __ldg(temp + j);
            bool t_ij, s_dummy, t_dummy, s_ji;
            pair_masks(mi, mj, sri, srj, ti, tj, t_ij, s_dummy);
            pair_masks(mj, mi, srj, sri, tj, ti, t_dummy, s_ji);
            if (t_ij || s_ji) {
                const float4* si = reinterpret_cast<const float4*>(pred + (size_t)i * S);
                const float4* sj = reinterpret_cast<const float4*>(pred + (size_t)j * S);
                const int S4 = S >> 2;
                float acc = 0.f;
                for (int k = lane; k < S4; k += 32) {
                    float4 a = si[k], bq = sj[k];
                    acc += reluf(a.x - bq.x) + reluf(a.y - bq.y)
                         + reluf(a.z - bq.z) + reluf(a.w - bq.w);
                }
                #pragma unroll
                for (int off = 16; off > 0; off >>= 1)
                    acc += __shfl_xor_sync(0xFFFFFFFFu, acc, off);
                if (lane == 0) g_pairD[i * B + j] = acc / (float)S;
            }
        }
        __syncthreads();
    }

    // =================== epilogue: last block finishes ===================
    __threadfence();
    if (tid == 0) {
        unsigned int v = atomicAdd(&g_ticket, 1u);
        sh_last = (v == gridDim.x - 1);
    }
    __syncthreads();
    if (!sh_last) return;
    __threadfence();

    // ---- final combine (runs in the last-arriving block, 256 threads) ----
    float mse_p = 0.f, el_sum = 0.f, el_cnt = 0.f, mono_p = 0.f;
    for (int b = tid; b < B; b += 256) {
        float mse = 0.f, cnt = 0.f, Sx = 0.f, Sy = 0.f, Sxy = 0.f, Sxx = 0.f, mono = 0.f;
        for (int c = 0; c < nChunk; c++) {
            const int slot = b * nChunk + c;
            mse += g_part[0][slot]; cnt += g_part[1][slot];
            Sx  += g_part[2][slot]; Sy  += g_part[3][slot];
            Sxy += g_part[4][slot]; Sxx += g_part[5][slot];
            mono+= g_part[6][slot];
        }
        mse_p  += (mse / (float)S) * w[mat[b]];
        mono_p += mono;
        if (cnt >= 2.f) {
            float safe  = fmaxf(cnt, 1.f);
            float eps_m = Sx / safe;
            float sig_m = Sy / safe;
            float cov = Sxy - sig_m * Sx - eps_m * Sy + cnt * eps_m * sig_m;
            float var = Sxx - 2.f * eps_m * Sx + cnt * eps_m * eps_m;
            float et  = E[b] * 1000.f;
            el_sum += fabsf(cov / (var + 1e-8f) - et) / (et + 1e-8f);
            el_cnt += 1.f;
        }
    }

    float tsum = 0.f, tcnt = 0.f, ssum = 0.f, scnt = 0.f;
    for (int idx = tid; idx < B * B; idx += 256) {
        const int i = idx / B;
        const int j = idx - i * B;
        bool t_ij, s_ij;
        pair_masks(mat[i], mat[j], sr[i], sr[j], temp[i], temp[j], t_ij, s_ij);
        if (t_ij) { tsum += g_pairD[i * B + j]; tcnt += 1.f; }
        if (s_ij) { ssum += g_pairD[j * B + i]; scnt += 1.f; }
    }

    sh[0][tid]=mse_p; sh[1][tid]=el_sum; sh[2][tid]=el_cnt; sh[3][tid]=mono_p;
    sh[4][tid]=tsum;  sh[5][tid]=tcnt;   sh[6][tid]=ssum;   sh[7][tid]=scnt;
    __syncthreads();
    for (int s = 128; s > 0; s >>= 1) {
        if (tid < s) {
            #pragma unroll
            for (int k = 0; k < 8; k++) sh[k][tid] += sh[k][tid + s];
        }
        __syncthreads();
    }

    if (tid == 0) {
        float mse_loss  = sh[0][0] / (float)B;
        float elastic   = (sh[2][0] > 0.f) ? sh[1][0] / fmaxf(sh[2][0], 1.f) : 0.f;
        float mono      = sh[3][0] / (float)(B * (S - 1));
        float temp_loss = (sh[5][0] > 0.f) ? sh[4][0] / fmaxf(sh[5][0], 1.f) : 0.f;
        float sr_loss   = (sh[7][0] > 0.f) ? sh[6][0] / fmaxf(sh[7][0], 1.f) : 0.f;
        out[0] = ALPHA * mse_loss + BETA * (elastic + mono + temp_loss + sr_loss);
        g_ticket = 0;   // reset for next graph replay (deterministic)
    }
}

// --------------------------------------------------------------------------
extern "C" void kernel_launch(void* const* d_in, const int* in_sizes, int n_in,
                              void* d_out, int out_size)
{
    const float* pred   = (const float*)d_in[0];
    const float* target = (const float*)d_in[1];
    const int*   matid  = (const int*)  d_in[2];
    const float* strain = (const float*)d_in[3];
    const float* E_GPa  = (const float*)d_in[4];
    const float* temp   = (const float*)d_in[5];
    const float* sr     = (const float*)d_in[6];
    const float* mw     = (const float*)d_in[7];
    float* out = (float*)d_out;

    const int B = in_sizes[2];          // material_ids count
    const int S = in_sizes[0] / B;      // pred = B*S

    const int nChunk      = (S + 1023) / 1024;       // 1024 elems per chunk
    const int statsBlocks = B * nChunk;               // 256 for B=128,S=2048
    const int pairBlocks  = (B * B + 7) / 8;          // 8 pairs (warps) / block
    const int grid        = statsBlocks + pairBlocks; // one fused launch

    fused_kernel<<<grid, 256>>>(pred, target, matid, strain, E_GPa, temp, sr, mw,
                                out, B, S, nChunk, statsBlocks, pairBlocks);
}